// round 9
// baseline (speedup 1.0000x reference)
#include <cuda_runtime.h>
#include <cstdint>

typedef unsigned long long ull;

#define D_DIM   128
#define K_DIM   32
#define N_PIX   4096
#define B_SZ    8
#define TILE_T  128
#define XSTRIDE 130   // x row stride: conflict-free LDS.64 rows (stage A) + LDS.32 columns (stage B)
#define CSTRIDE 132   // codeword row stride (16B aligned rows)
#define ASTRIDE 34    // A / Ered row stride in floats (17 ulls)

// shared-memory layout (float offsets)
#define X_OFF    0
#define C_OFF    (TILE_T * XSTRIDE)                  // 16640
#define A_OFF    (C_OFF + K_DIM * CSTRIDE)           // 20864 (ull aligned)
#define XSQ_OFF  (A_OFF + TILE_T * ASTRIDE)          // 25216
#define S_OFF    (XSQ_OFF + TILE_T)                  // 25344
#define BK_OFF   (S_OFF + K_DIM)                     // 25376
#define WAS_OFF  (BK_OFF + K_DIM)                    // 25408
#define ASUM_OFF (WAS_OFF + 8 * K_DIM)               // 25664
#define SMEM_FLOATS (ASUM_OFF + K_DIM)               // 25696
#define SMEM_BYTES  (SMEM_FLOATS * 4)                // 102784 B -> 2 blocks/SM, single wave @ grid 256

// packed fp32x2 FMA (Blackwell): acc.lo += a.lo*b.lo ; acc.hi += a.hi*b.hi
__device__ __forceinline__ void ffma2(ull &acc, ull a, ull b) {
    asm("fma.rn.f32x2 %0, %1, %2, %0;" : "+l"(acc) : "l"(a), "l"(b));
}
__device__ __forceinline__ float2 u2f(ull v) {
    float2 r;
    asm("mov.b64 {%0, %1}, %2;" : "=f"(r.x), "=f"(r.y) : "l"(v));
    return r;
}
__device__ __forceinline__ ull f2u(float x, float y) {
    ull v;
    asm("mov.b64 %0, {%1, %2};" : "=l"(v) : "f"(x), "f"(y));
    return v;
}
__device__ __forceinline__ void cpa4(uint32_t s, const void* g) {
    asm volatile("cp.async.ca.shared.global [%0], [%1], 4;" :: "r"(s), "l"(g));
}
__device__ __forceinline__ void cpa16(uint32_t s, const void* g) {
    asm volatile("cp.async.cg.shared.global [%0], [%1], 16;" :: "r"(s), "l"(g));
}

__global__ void zero_kernel(float4* p, int n4) {
    int i = blockIdx.x * blockDim.x + threadIdx.x;
    if (i < n4) p[i] = make_float4(0.f, 0.f, 0.f, 0.f);
}

__global__ void __launch_bounds__(256, 2)
enc_kernel(const float* __restrict__ X,
           const float* __restrict__ CW,
           const float* __restrict__ SC,
           float* __restrict__ out)
{
    extern __shared__ float sm[];

    const int tid  = threadIdx.x;
    const int w    = tid >> 5;
    const int l    = tid & 31;
    const int b    = blockIdx.x >> 5;      // batch (32 tiles per batch)
    const int tile = blockIdx.x & 31;
    const int n0   = tile * TILE_T;

    // ---- async load: X tile [128 d][128 t] transposed into x_sh[t][130], C into c_sh ----
    {
        const uint32_t smem_u32 = (uint32_t)__cvta_generic_to_shared(sm);
        const float* Xb = X + (size_t)b * D_DIM * N_PIX + n0;
        const int tl = tid & 127;          // pixel (lanes contiguous -> coalesced)
        const int dh = tid >> 7;
        #pragma unroll
        for (int s = 0; s < 64; s++) {
            int d = dh + 2 * s;
            cpa4(smem_u32 + (uint32_t)(X_OFF + tl * XSTRIDE + d) * 4,
                 Xb + (size_t)d * N_PIX + tl);
        }
        #pragma unroll
        for (int s = 0; s < 4; s++) {
            int c = tid + 256 * s;             // 0..1023 chunks of 4 floats
            int k = c >> 5;
            int dc = (c & 31) * 4;
            cpa16(smem_u32 + (uint32_t)(C_OFF + k * CSTRIDE + dc) * 4, CW + 4 * c);
        }
        asm volatile("cp.async.commit_group;" ::: "memory");
        asm volatile("cp.async.wait_group 0;" ::: "memory");
    }
    __syncthreads();

    // ---- xsq per pixel: warp w handles rows [w*16, w*16+16) ----
    #pragma unroll
    for (int p = 0; p < 16; p++) {
        int t = w * 16 + p;
        const float* row = sm + X_OFF + t * XSTRIDE;
        float2 v0 = *(const float2*)(row + 2 * l);
        float2 v1 = *(const float2*)(row + 64 + 2 * l);
        float ss = v0.x * v0.x + v0.y * v0.y + v1.x * v1.x + v1.y * v1.y;
        #pragma unroll
        for (int o = 16; o > 0; o >>= 1) ss += __shfl_xor_sync(0xffffffffu, ss, o);
        if (l == 0) sm[XSQ_OFF + t] = ss;
    }
    // ---- csq*scale and scale per codeword: warp w handles k = 4w..4w+3 ----
    #pragma unroll
    for (int jj = 0; jj < 4; jj++) {
        int k = 4 * w + jj;
        const float* row = sm + C_OFF + k * CSTRIDE;
        float2 v0 = *(const float2*)(row + 2 * l);
        float2 v1 = *(const float2*)(row + 64 + 2 * l);
        float ss = v0.x * v0.x + v0.y * v0.y + v1.x * v1.x + v1.y * v1.y;
        #pragma unroll
        for (int o = 16; o > 0; o >>= 1) ss += __shfl_xor_sync(0xffffffffu, ss, o);
        if (l == 0) {
            float sc = SC[k];
            sm[S_OFF + k]  = sc;
            sm[BK_OFF + k] = ss * sc;
        }
    }
    __syncthreads();

    // ---- Stage A: cross[t][k] = sum_d x[t][d]*c[k][d]; 8t x 4k tile, d-pair acc, 2-way d split ----
    const int g  = w >> 2;
    const int tb = l & 31 & 15;
    const int lh = l >> 4;
    {
        const int kb = 2 * (w & 3) + lh;

        ull acc[8][4];
        #pragma unroll
        for (int i = 0; i < 8; i++)
            #pragma unroll
            for (int jj = 0; jj < 4; jj++) acc[i][jj] = 0ULL;

        const float* xr = sm + X_OFF + tb * XSTRIDE + 64 * g;
        const float* cr = sm + C_OFF + (4 * kb) * CSTRIDE + 64 * g;

        #pragma unroll 2
        for (int dp = 0; dp < 32; dp++) {
            ull cv[4];
            #pragma unroll
            for (int jj = 0; jj < 4; jj++)
                cv[jj] = *(const ull*)(cr + jj * CSTRIDE + 2 * dp);
            #pragma unroll
            for (int i = 0; i < 8; i++) {
                ull xv = *(const ull*)(xr + (16 * i) * XSTRIDE + 2 * dp);
                ffma2(acc[i][0], xv, cv[0]);
                ffma2(acc[i][1], xv, cv[1]);
                ffma2(acc[i][2], xv, cv[2]);
                ffma2(acc[i][3], xv, cv[3]);
            }
        }

        // dual-half combine: group g writes partials for i-half W(g), finalizes the other half.
        // W(1) = i 0..3 (t<64), W(0) = i 4..7 (t>=64).
        const int iw0 = g ? 0 : 4;
        #pragma unroll
        for (int i2 = 0; i2 < 4; i2++) {
            int i = iw0 + i2;
            int t = tb + 16 * i;
            #pragma unroll
            for (int jp = 0; jp < 2; jp++) {
                float2 p0 = u2f(acc[i][2 * jp]);
                float2 p1 = u2f(acc[i][2 * jp + 1]);
                *(ull*)(sm + A_OFF + t * ASTRIDE + 4 * kb + 2 * jp) =
                    f2u(p0.x + p0.y, p1.x + p1.y);
            }
        }
        __syncthreads();
        {
            float sv[4], bv[4];
            #pragma unroll
            for (int jj = 0; jj < 4; jj++) {
                sv[jj] = sm[S_OFF + 4 * kb + jj];
                bv[jj] = sm[BK_OFF + 4 * kb + jj];
            }
            const int if0 = g ? 4 : 0;
            #pragma unroll
            for (int i2 = 0; i2 < 4; i2++) {
                int i = if0 + i2;
                int t = tb + 16 * i;
                float xsq = sm[XSQ_OFF + t];
                #pragma unroll
                for (int jp = 0; jp < 2; jp++) {
                    ull* addr = (ull*)(sm + A_OFF + t * ASTRIDE + 4 * kb + 2 * jp);
                    float2 oth = u2f(*addr);
                    float2 p0 = u2f(acc[i][2 * jp]);
                    float2 p1 = u2f(acc[i][2 * jp + 1]);
                    float cr0 = oth.x + p0.x + p0.y;
                    float cr1 = oth.y + p1.x + p1.y;
                    float lg0 = fmaf(sv[2 * jp],     fmaf(-2.0f, cr0, xsq), bv[2 * jp]);
                    float lg1 = fmaf(sv[2 * jp + 1], fmaf(-2.0f, cr1, xsq), bv[2 * jp + 1]);
                    *addr = f2u(lg0, lg1);
                }
            }
        }
    }
    __syncthreads();

    // ---- Softmax over k (lane = k): warp w handles px [16w, 16w+16); no max pass ----
    {
        float asum_l = 0.0f;
        #pragma unroll
        for (int q = 0; q < 4; q++) {
            int t0 = w * 16 + 4 * q;
            float v0 = sm[A_OFF + (t0 + 0) * ASTRIDE + l];
            float v1 = sm[A_OFF + (t0 + 1) * ASTRIDE + l];
            float v2 = sm[A_OFF + (t0 + 2) * ASTRIDE + l];
            float v3 = sm[A_OFF + (t0 + 3) * ASTRIDE + l];
            float e0 = __expf(v0), e1 = __expf(v1);
            float e2 = __expf(v2), e3 = __expf(v3);
            float s0 = e0, s1 = e1, s2 = e2, s3 = e3;
            #pragma unroll
            for (int o = 16; o > 0; o >>= 1) {
                s0 += __shfl_xor_sync(0xffffffffu, s0, o);
                s1 += __shfl_xor_sync(0xffffffffu, s1, o);
                s2 += __shfl_xor_sync(0xffffffffu, s2, o);
                s3 += __shfl_xor_sync(0xffffffffu, s3, o);
            }
            float a0 = e0 * __fdividef(1.0f, s0);
            float a1 = e1 * __fdividef(1.0f, s1);
            float a2 = e2 * __fdividef(1.0f, s2);
            float a3 = e3 * __fdividef(1.0f, s3);
            sm[A_OFF + (t0 + 0) * ASTRIDE + l] = a0;
            sm[A_OFF + (t0 + 1) * ASTRIDE + l] = a1;
            sm[A_OFF + (t0 + 2) * ASTRIDE + l] = a2;
            sm[A_OFF + (t0 + 3) * ASTRIDE + l] = a3;
            asum_l += a0 + a1 + a2 + a3;
        }
        sm[WAS_OFF + w * 32 + l] = asum_l;
    }
    __syncthreads();
    if (tid < 32) {
        float a = 0.0f;
        #pragma unroll
        for (int ww = 0; ww < 8; ww++) a += sm[WAS_OFF + ww * 32 + tid];
        sm[ASUM_OFF + tid] = a;
    }
    __syncthreads();

    // ---- Stage B: E[k][d] = sum_t A[k][t]*x[t][d]; 8k x 4d tile, k-pair acc, 2-way t split ----
    {
        const int gB  = w >> 2;
        const int kbB = w & 3;
        const int db  = l;

        ull acc2[4][4];
        #pragma unroll
        for (int jj = 0; jj < 4; jj++)
            #pragma unroll
            for (int j = 0; j < 4; j++) acc2[jj][j] = 0ULL;

        const int t0 = 64 * gB;
        #pragma unroll 4
        for (int tt = 0; tt < 64; tt++) {
            int t = t0 + tt;
            const float* xrow = sm + X_OFF + t * XSTRIDE + db;
            ull xx[4];
            #pragma unroll
            for (int j = 0; j < 4; j++) {
                float xv = xrow[32 * j];
                xx[j] = f2u(xv, xv);
            }
            const float* Ar = sm + A_OFF + t * ASTRIDE + 8 * kbB;
            ull av0 = *(const ull*)(Ar + 0);
            ull av1 = *(const ull*)(Ar + 2);
            ull av2 = *(const ull*)(Ar + 4);
            ull av3 = *(const ull*)(Ar + 6);
            #pragma unroll
            for (int j = 0; j < 4; j++) {
                ffma2(acc2[0][j], av0, xx[j]);
                ffma2(acc2[1][j], av1, xx[j]);
                ffma2(acc2[2][j], av2, xx[j]);
                ffma2(acc2[3][j], av3, xx[j]);
            }
        }
        __syncthreads();           // all A reads done; A region becomes Ered[d][k]

        // dual-half exchange: group gB writes jj-half W(gB), finalizes the other half.
        // W(0) = jj{0,1}, W(1) = jj{2,3}.
        const int jw0 = gB ? 2 : 0;
        #pragma unroll
        for (int j2 = 0; j2 < 2; j2++) {
            int jj = jw0 + j2;
            #pragma unroll
            for (int j = 0; j < 4; j++) {
                int d = db + 32 * j;
                *(ull*)(sm + A_OFF + d * ASTRIDE + 8 * kbB + 2 * jj) = acc2[jj][j];
            }
        }
        __syncthreads();
        {
            float* Eb = out + (size_t)b * K_DIM * D_DIM;
            const int jf0 = gB ? 0 : 2;
            #pragma unroll
            for (int j2 = 0; j2 < 2; j2++) {
                int jj = jf0 + j2;
                int k0 = 8 * kbB + 2 * jj;
                float as0 = sm[ASUM_OFF + k0];
                float as1 = sm[ASUM_OFF + k0 + 1];
                #pragma unroll
                for (int j = 0; j < 4; j++) {
                    int d = db + 32 * j;
                    float2 mine = u2f(acc2[jj][j]);
                    float2 oth  = u2f(*(const ull*)(sm + A_OFF + d * ASTRIDE + k0));
                    float v0 = fmaf(-as0, sm[C_OFF + k0 * CSTRIDE + d],       mine.x + oth.x);
                    float v1 = fmaf(-as1, sm[C_OFF + (k0 + 1) * CSTRIDE + d], mine.y + oth.y);
                    atomicAdd(Eb + k0 * D_DIM + d,       v0);
                    atomicAdd(Eb + (k0 + 1) * D_DIM + d, v1);
                }
            }
        }
    }
}

extern "C" void kernel_launch(void* const* d_in, const int* in_sizes, int n_in,
                              void* d_out, int out_size)
{
    const float* X  = (const float*)d_in[0];
    const float* CW = (const float*)d_in[1];
    const float* SC = (const float*)d_in[2];
    float* out = (float*)d_out;

    cudaFuncSetAttribute(enc_kernel, cudaFuncAttributeMaxDynamicSharedMemorySize, SMEM_BYTES);

    const int OUT_N4 = (B_SZ * K_DIM * D_DIM) / 4;      // 8192 float4
    zero_kernel<<<OUT_N4 / 256, 256>>>((float4*)out, OUT_N4);
    enc_kernel<<<B_SZ * (N_PIX / TILE_T), 256, SMEM_BYTES>>>(X, CW, SC, out);
}

// round 10
// speedup vs baseline: 1.0600x; 1.0600x over previous
#include <cuda_runtime.h>
#include <cstdint>

typedef unsigned long long ull;

#define D_DIM   128
#define K_DIM   32
#define N_PIX   4096
#define B_SZ    8
#define TILE_T  128
#define XSTRIDE 130   // x row stride: conflict-free LDS.64 rows (stage A) + LDS.32 columns (stage B)
#define CSTRIDE 132   // codeword row stride (16B aligned rows)
#define ASTRIDE 34    // A / Ered row stride in floats (17 ulls)

// shared-memory layout (float offsets)
#define X_OFF    0
#define C_OFF    (TILE_T * XSTRIDE)                  // 16640
#define A_OFF    (C_OFF + K_DIM * CSTRIDE)           // 20864 (ull aligned)
#define XSQ_OFF  (A_OFF + TILE_T * ASTRIDE)          // 25216
#define XSP_OFF  (XSQ_OFF + TILE_T)                  // 25344 (2 x 128 partials)
#define S_OFF    (XSP_OFF + 2 * TILE_T)              // 25600
#define BK_OFF   (S_OFF + K_DIM)                     // 25632
#define WAS_OFF  (BK_OFF + K_DIM)                    // 25664
#define ASUM_OFF (WAS_OFF + 8 * K_DIM)               // 25920
#define SMEM_FLOATS (ASUM_OFF + K_DIM)               // 25952
#define SMEM_BYTES  (SMEM_FLOATS * 4)                // 103808 B -> 2 blocks/SM, single wave @ grid 256

// packed fp32x2 FMA (Blackwell): acc.lo += a.lo*b.lo ; acc.hi += a.hi*b.hi
__device__ __forceinline__ void ffma2(ull &acc, ull a, ull b) {
    asm("fma.rn.f32x2 %0, %1, %2, %0;" : "+l"(acc) : "l"(a), "l"(b));
}
__device__ __forceinline__ float2 u2f(ull v) {
    float2 r;
    asm("mov.b64 {%0, %1}, %2;" : "=f"(r.x), "=f"(r.y) : "l"(v));
    return r;
}
__device__ __forceinline__ ull f2u(float x, float y) {
    ull v;
    asm("mov.b64 %0, {%1, %2};" : "=l"(v) : "f"(x), "f"(y));
    return v;
}

__global__ void __launch_bounds__(256, 2)
enc_kernel(const float* __restrict__ X,
           const float* __restrict__ CW,
           const float* __restrict__ SC,
           float* __restrict__ out)
{
    extern __shared__ float sm[];

    const int tid  = threadIdx.x;
    const int w    = tid >> 5;
    const int l    = tid & 31;
    const int b    = blockIdx.x >> 5;      // batch (32 tiles per batch)
    const int tile = blockIdx.x & 31;
    const int n0   = tile * TILE_T;

    // ---- load X tile [128 d][128 t] -> x_sh[t][130], folding per-pixel x^2 partials ----
    // thread: t = tid&127 (fixed), d = (tid>>7) + 2*s  -> each thread owns 64 d's of one pixel.
    {
        const float* Xb = X + (size_t)b * D_DIM * N_PIX + n0;
        const int tl = tid & 127;
        const int dh = tid >> 7;
        float ssq = 0.0f;
        #pragma unroll 8
        for (int s = 0; s < 64; s++) {
            int d = dh + 2 * s;
            float v = Xb[(size_t)d * N_PIX + tl];
            sm[X_OFF + tl * XSTRIDE + d] = v;
            ssq = fmaf(v, v, ssq);
        }
        sm[XSP_OFF + dh * TILE_T + tl] = ssq;

        // codewords: float4 loads (4 LDG.128 per thread)
        #pragma unroll
        for (int s = 0; s < 4; s++) {
            int c = tid + 256 * s;             // 0..1023 quads
            int k = c >> 5;
            int dc = (c & 31) * 4;
            float4 v = *(const float4*)(CW + 4 * c);
            *(float4*)(sm + C_OFF + k * CSTRIDE + dc) = v;
        }
    }
    __syncthreads();

    // ---- finalize xsq; csq*scale per codeword ----
    if (tid < TILE_T)
        sm[XSQ_OFF + tid] = sm[XSP_OFF + tid] + sm[XSP_OFF + TILE_T + tid];
    #pragma unroll
    for (int jj = 0; jj < 4; jj++) {
        int k = 4 * w + jj;
        const float* row = sm + C_OFF + k * CSTRIDE;
        float2 v0 = *(const float2*)(row + 2 * l);
        float2 v1 = *(const float2*)(row + 64 + 2 * l);
        float ss = v0.x * v0.x + v0.y * v0.y + v1.x * v1.x + v1.y * v1.y;
        #pragma unroll
        for (int o = 16; o > 0; o >>= 1) ss += __shfl_xor_sync(0xffffffffu, ss, o);
        if (l == 0) {
            float sc = SC[k];
            sm[S_OFF + k]  = sc;
            sm[BK_OFF + k] = ss * sc;
        }
    }
    __syncthreads();

    // ---- Stage A: cross[t][k] = sum_d x[t][d]*c[k][d]; 8t x 4k tile, d-pair acc, 2-way d split ----
    // g = w>>2 (d-half 64), lanes: tb = l&15, lh = l>>4; kb = 2*(w&3)+lh in [0,8); k = 4kb+jj.
    const int g  = w >> 2;
    const int tb = l & 15;
    const int lh = l >> 4;
    {
        const int kb = 2 * (w & 3) + lh;

        ull acc[8][4];
        #pragma unroll
        for (int i = 0; i < 8; i++)
            #pragma unroll
            for (int jj = 0; jj < 4; jj++) acc[i][jj] = 0ULL;

        const float* xr = sm + X_OFF + tb * XSTRIDE + 64 * g;
        const float* cr = sm + C_OFF + (4 * kb) * CSTRIDE + 64 * g;

        #pragma unroll 2
        for (int dp = 0; dp < 32; dp++) {
            ull cv[4];
            #pragma unroll
            for (int jj = 0; jj < 4; jj++)
                cv[jj] = *(const ull*)(cr + jj * CSTRIDE + 2 * dp);
            #pragma unroll
            for (int i = 0; i < 8; i++) {
                ull xv = *(const ull*)(xr + (16 * i) * XSTRIDE + 2 * dp);
                ffma2(acc[i][0], xv, cv[0]);
                ffma2(acc[i][1], xv, cv[1]);
                ffma2(acc[i][2], xv, cv[2]);
                ffma2(acc[i][3], xv, cv[3]);
            }
        }

        // dual-half combine: group g writes partials for i-half W(g), finalizes the other half.
        // W(1) = i 0..3 (t<64), W(0) = i 4..7 (t>=64).
        const int iw0 = g ? 0 : 4;
        #pragma unroll
        for (int i2 = 0; i2 < 4; i2++) {
            int i = iw0 + i2;
            int t = tb + 16 * i;
            #pragma unroll
            for (int jp = 0; jp < 2; jp++) {
                float2 p0 = u2f(acc[i][2 * jp]);
                float2 p1 = u2f(acc[i][2 * jp + 1]);
                *(ull*)(sm + A_OFF + t * ASTRIDE + 4 * kb + 2 * jp) =
                    f2u(p0.x + p0.y, p1.x + p1.y);
            }
        }
        __syncthreads();
        {
            float sv[4], bv[4];
            #pragma unroll
            for (int jj = 0; jj < 4; jj++) {
                sv[jj] = sm[S_OFF + 4 * kb + jj];
                bv[jj] = sm[BK_OFF + 4 * kb + jj];
            }
            const int if0 = g ? 4 : 0;
            #pragma unroll
            for (int i2 = 0; i2 < 4; i2++) {
                int i = if0 + i2;
                int t = tb + 16 * i;
                float xsq = sm[XSQ_OFF + t];
                #pragma unroll
                for (int jp = 0; jp < 2; jp++) {
                    ull* addr = (ull*)(sm + A_OFF + t * ASTRIDE + 4 * kb + 2 * jp);
                    float2 oth = u2f(*addr);
                    float2 p0 = u2f(acc[i][2 * jp]);
                    float2 p1 = u2f(acc[i][2 * jp + 1]);
                    float cr0 = oth.x + p0.x + p0.y;
                    float cr1 = oth.y + p1.x + p1.y;
                    float lg0 = fmaf(sv[2 * jp],     fmaf(-2.0f, cr0, xsq), bv[2 * jp]);
                    float lg1 = fmaf(sv[2 * jp + 1], fmaf(-2.0f, cr1, xsq), bv[2 * jp + 1]);
                    *addr = f2u(lg0, lg1);
                }
            }
        }
    }
    __syncthreads();

    // ---- Softmax over k (lane = k): warp w handles px [16w, 16w+16); no max pass ----
    {
        float asum_l = 0.0f;
        #pragma unroll
        for (int q = 0; q < 4; q++) {
            int t0 = w * 16 + 4 * q;
            float v0 = sm[A_OFF + (t0 + 0) * ASTRIDE + l];
            float v1 = sm[A_OFF + (t0 + 1) * ASTRIDE + l];
            float v2 = sm[A_OFF + (t0 + 2) * ASTRIDE + l];
            float v3 = sm[A_OFF + (t0 + 3) * ASTRIDE + l];
            float e0 = __expf(v0), e1 = __expf(v1);
            float e2 = __expf(v2), e3 = __expf(v3);
            float s0 = e0, s1 = e1, s2 = e2, s3 = e3;
            #pragma unroll
            for (int o = 16; o > 0; o >>= 1) {
                s0 += __shfl_xor_sync(0xffffffffu, s0, o);
                s1 += __shfl_xor_sync(0xffffffffu, s1, o);
                s2 += __shfl_xor_sync(0xffffffffu, s2, o);
                s3 += __shfl_xor_sync(0xffffffffu, s3, o);
            }
            float a0 = e0 * __fdividef(1.0f, s0);
            float a1 = e1 * __fdividef(1.0f, s1);
            float a2 = e2 * __fdividef(1.0f, s2);
            float a3 = e3 * __fdividef(1.0f, s3);
            sm[A_OFF + (t0 + 0) * ASTRIDE + l] = a0;
            sm[A_OFF + (t0 + 1) * ASTRIDE + l] = a1;
            sm[A_OFF + (t0 + 2) * ASTRIDE + l] = a2;
            sm[A_OFF + (t0 + 3) * ASTRIDE + l] = a3;
            asum_l += a0 + a1 + a2 + a3;
        }
        sm[WAS_OFF + w * 32 + l] = asum_l;
    }
    __syncthreads();
    if (tid < 32) {
        float a = 0.0f;
        #pragma unroll
        for (int ww = 0; ww < 8; ww++) a += sm[WAS_OFF + ww * 32 + tid];
        sm[ASUM_OFF + tid] = a;
    }
    __syncthreads();

    // ---- Stage B: E[k][d] = sum_t A[k][t]*x[t][d]; 8k x 4d tile, k-pair acc, 2-way t split ----
    {
        const int gB  = w >> 2;
        const int kbB = w & 3;
        const int db  = l;

        ull acc2[4][4];
        #pragma unroll
        for (int jj = 0; jj < 4; jj++)
            #pragma unroll
            for (int j = 0; j < 4; j++) acc2[jj][j] = 0ULL;

        const int t0 = 64 * gB;
        #pragma unroll 4
        for (int tt = 0; tt < 64; tt++) {
            int t = t0 + tt;
            const float* xrow = sm + X_OFF + t * XSTRIDE + db;
            ull xx[4];
            #pragma unroll
            for (int j = 0; j < 4; j++) {
                float xv = xrow[32 * j];
                xx[j] = f2u(xv, xv);
            }
            const float* Ar = sm + A_OFF + t * ASTRIDE + 8 * kbB;
            ull av0 = *(const ull*)(Ar + 0);
            ull av1 = *(const ull*)(Ar + 2);
            ull av2 = *(const ull*)(Ar + 4);
            ull av3 = *(const ull*)(Ar + 6);
            #pragma unroll
            for (int j = 0; j < 4; j++) {
                ffma2(acc2[0][j], av0, xx[j]);
                ffma2(acc2[1][j], av1, xx[j]);
                ffma2(acc2[2][j], av2, xx[j]);
                ffma2(acc2[3][j], av3, xx[j]);
            }
        }
        __syncthreads();           // all A reads done; A region becomes Ered[d][k]

        // dual-half exchange: group gB writes jj-half W(gB), finalizes the other half.
        // W(0) = jj{0,1}, W(1) = jj{2,3}.
        const int jw0 = gB ? 2 : 0;
        #pragma unroll
        for (int j2 = 0; j2 < 2; j2++) {
            int jj = jw0 + j2;
            #pragma unroll
            for (int j = 0; j < 4; j++) {
                int d = db + 32 * j;
                *(ull*)(sm + A_OFF + d * ASTRIDE + 8 * kbB + 2 * jj) = acc2[jj][j];
            }
        }
        __syncthreads();
        {
            float* Eb = out + (size_t)b * K_DIM * D_DIM;
            const int jf0 = gB ? 0 : 2;
            #pragma unroll
            for (int j2 = 0; j2 < 2; j2++) {
                int jj = jf0 + j2;
                int k0 = 8 * kbB + 2 * jj;
                float as0 = sm[ASUM_OFF + k0];
                float as1 = sm[ASUM_OFF + k0 + 1];
                #pragma unroll
                for (int j = 0; j < 4; j++) {
                    int d = db + 32 * j;
                    float2 mine = u2f(acc2[jj][j]);
                    float2 oth  = u2f(*(const ull*)(sm + A_OFF + d * ASTRIDE + k0));
                    float v0 = fmaf(-as0, sm[C_OFF + k0 * CSTRIDE + d],       mine.x + oth.x);
                    float v1 = fmaf(-as1, sm[C_OFF + (k0 + 1) * CSTRIDE + d], mine.y + oth.y);
                    atomicAdd(Eb + k0 * D_DIM + d,       v0);
                    atomicAdd(Eb + (k0 + 1) * D_DIM + d, v1);
                }
            }
        }
    }
}

extern "C" void kernel_launch(void* const* d_in, const int* in_sizes, int n_in,
                              void* d_out, int out_size)
{
    const float* X  = (const float*)d_in[0];
    const float* CW = (const float*)d_in[1];
    const float* SC = (const float*)d_in[2];
    float* out = (float*)d_out;

    cudaFuncSetAttribute(enc_kernel, cudaFuncAttributeMaxDynamicSharedMemorySize, SMEM_BYTES);

    // zero E via async memset (graph-capturable, no extra kernel launch)
    cudaMemsetAsync(out, 0, (size_t)B_SZ * K_DIM * D_DIM * sizeof(float));
    enc_kernel<<<B_SZ * (N_PIX / TILE_T), 256, SMEM_BYTES>>>(X, CW, SC, out);
}

// round 11
// speedup vs baseline: 1.1925x; 1.1250x over previous
#include <cuda_runtime.h>
#include <cstdint>

typedef unsigned long long ull;

#define D_DIM   128
#define K_DIM   32
#define N_PIX   4096
#define B_SZ    8
#define TILE_T  128
#define XSTRIDE 130   // x row stride: conflict-free LDS.64 rows (stage A) + LDS.32 columns (stage B)
#define CSTRIDE 132   // codeword row stride (16B aligned rows)
#define ASTRIDE 34    // A / Ered row stride in floats (17 ulls)

// shared-memory layout (float offsets)
#define X_OFF    0
#define C_OFF    (TILE_T * XSTRIDE)                  // 16640
#define A_OFF    (C_OFF + K_DIM * CSTRIDE)           // 20864 (ull aligned)
#define XSQ_OFF  (A_OFF + TILE_T * ASTRIDE)          // 25216
#define XSP_OFF  (XSQ_OFF + TILE_T)                  // 25344 (2 x 128 partials)
#define S_OFF    (XSP_OFF + 2 * TILE_T)              // 25600
#define BK_OFF   (S_OFF + K_DIM)                     // 25632
#define WAS_OFF  (BK_OFF + K_DIM)                    // 25664
#define ASUM_OFF (WAS_OFF + 8 * K_DIM)               // 25920
#define SMEM_FLOATS (ASUM_OFF + K_DIM)               // 25952
#define SMEM_BYTES  (SMEM_FLOATS * 4)                // 103808 B -> 2 blocks/SM, single wave @ grid 256

// packed fp32x2 FMA (Blackwell): acc.lo += a.lo*b.lo ; acc.hi += a.hi*b.hi
__device__ __forceinline__ void ffma2(ull &acc, ull a, ull b) {
    asm("fma.rn.f32x2 %0, %1, %2, %0;" : "+l"(acc) : "l"(a), "l"(b));
}
__device__ __forceinline__ float2 u2f(ull v) {
    float2 r;
    asm("mov.b64 {%0, %1}, %2;" : "=f"(r.x), "=f"(r.y) : "l"(v));
    return r;
}
__device__ __forceinline__ ull f2u(float x, float y) {
    ull v;
    asm("mov.b64 %0, {%1, %2};" : "=l"(v) : "f"(x), "f"(y));
    return v;
}

__global__ void __launch_bounds__(256, 2)
enc_kernel(const float* __restrict__ X,
           const float* __restrict__ CW,
           const float* __restrict__ SC,
           float* __restrict__ out)
{
    extern __shared__ float sm[];

    const int tid  = threadIdx.x;
    const int w    = tid >> 5;
    const int l    = tid & 31;
    const int b    = blockIdx.x >> 5;      // batch (32 tiles per batch)
    const int tile = blockIdx.x & 31;
    const int n0   = tile * TILE_T;

    // ---- load X tile [128 d][128 t] -> x_sh[t][130], folding per-pixel x^2 partials ----
    // thread: t = tid&127 (fixed), d = (tid>>7) + 2*s  -> each thread owns 64 d's of one pixel.
    {
        const float* Xb = X + (size_t)b * D_DIM * N_PIX + n0;
        const int tl = tid & 127;
        const int dh = tid >> 7;
        float ssq = 0.0f;
        #pragma unroll 8
        for (int s = 0; s < 64; s++) {
            int d = dh + 2 * s;
            float v = Xb[(size_t)d * N_PIX + tl];
            sm[X_OFF + tl * XSTRIDE + d] = v;
            ssq = fmaf(v, v, ssq);
        }
        sm[XSP_OFF + dh * TILE_T + tl] = ssq;

        // codewords: float4 path (4 LDG.128 + 4 STS.128 per thread, coalesced, conflict-free)
        #pragma unroll
        for (int s = 0; s < 4; s++) {
            int c = tid + 256 * s;             // 0..1023 quads
            int k = c >> 5;
            int dc = (c & 31) * 4;
            float4 v = *(const float4*)(CW + 4 * c);
            *(float4*)(sm + C_OFF + k * CSTRIDE + dc) = v;
        }
    }
    __syncthreads();

    // ---- finalize xsq; csq*scale per codeword ----
    if (tid < TILE_T)
        sm[XSQ_OFF + tid] = sm[XSP_OFF + tid] + sm[XSP_OFF + TILE_T + tid];
    #pragma unroll
    for (int jj = 0; jj < 4; jj++) {
        int k = 4 * w + jj;
        const float* row = sm + C_OFF + k * CSTRIDE;
        float2 v0 = *(const float2*)(row + 2 * l);
        float2 v1 = *(const float2*)(row + 64 + 2 * l);
        float ss = v0.x * v0.x + v0.y * v0.y + v1.x * v1.x + v1.y * v1.y;
        #pragma unroll
        for (int o = 16; o > 0; o >>= 1) ss += __shfl_xor_sync(0xffffffffu, ss, o);
        if (l == 0) {
            float sc = SC[k];
            sm[S_OFF + k]  = sc;
            sm[BK_OFF + k] = ss * sc;
        }
    }
    __syncthreads();

    // ---- Stage A: cross[t][k] = sum_d x[t][d]*c[k][d]; 8t x 4k tile, d-pair acc, 2-way d split ----
    // g = w>>2 (d-half 64), lanes: tb = l&15, lh = l>>4; kb = 2*(w&3)+lh in [0,8); k = 4kb+jj.
    const int g  = w >> 2;
    const int tb = l & 15;
    const int lh = l >> 4;
    {
        const int kb = 2 * (w & 3) + lh;

        ull acc[8][4];
        #pragma unroll
        for (int i = 0; i < 8; i++)
            #pragma unroll
            for (int jj = 0; jj < 4; jj++) acc[i][jj] = 0ULL;

        const float* xr = sm + X_OFF + tb * XSTRIDE + 64 * g;
        const float* cr = sm + C_OFF + (4 * kb) * CSTRIDE + 64 * g;

        #pragma unroll 2
        for (int dp = 0; dp < 32; dp++) {
            ull cv[4];
            #pragma unroll
            for (int jj = 0; jj < 4; jj++)
                cv[jj] = *(const ull*)(cr + jj * CSTRIDE + 2 * dp);
            #pragma unroll
            for (int i = 0; i < 8; i++) {
                ull xv = *(const ull*)(xr + (16 * i) * XSTRIDE + 2 * dp);
                ffma2(acc[i][0], xv, cv[0]);
                ffma2(acc[i][1], xv, cv[1]);
                ffma2(acc[i][2], xv, cv[2]);
                ffma2(acc[i][3], xv, cv[3]);
            }
        }

        // g==1 writes partial cross pairs (k,k+1) into A[t][k] (float offset = k)
        if (g == 1) {
            #pragma unroll
            for (int i = 0; i < 8; i++) {
                int t = tb + 16 * i;
                #pragma unroll
                for (int jp = 0; jp < 2; jp++) {
                    float2 p0 = u2f(acc[i][2 * jp]);
                    float2 p1 = u2f(acc[i][2 * jp + 1]);
                    *(ull*)(sm + A_OFF + t * ASTRIDE + 4 * kb + 2 * jp) =
                        f2u(p0.x + p0.y, p1.x + p1.y);
                }
            }
        }
        __syncthreads();
        // g==0 adds its partial, computes logits, writes back in place
        if (g == 0) {
            float sv[4], bv[4];
            #pragma unroll
            for (int jj = 0; jj < 4; jj++) {
                sv[jj] = sm[S_OFF + 4 * kb + jj];
                bv[jj] = sm[BK_OFF + 4 * kb + jj];
            }
            #pragma unroll
            for (int i = 0; i < 8; i++) {
                int t = tb + 16 * i;
                float xsq = sm[XSQ_OFF + t];
                #pragma unroll
                for (int jp = 0; jp < 2; jp++) {
                    ull* addr = (ull*)(sm + A_OFF + t * ASTRIDE + 4 * kb + 2 * jp);
                    float2 oth = u2f(*addr);
                    float2 p0 = u2f(acc[i][2 * jp]);
                    float2 p1 = u2f(acc[i][2 * jp + 1]);
                    float cr0 = oth.x + p0.x + p0.y;
                    float cr1 = oth.y + p1.x + p1.y;
                    float lg0 = fmaf(sv[2 * jp],     fmaf(-2.0f, cr0, xsq), bv[2 * jp]);
                    float lg1 = fmaf(sv[2 * jp + 1], fmaf(-2.0f, cr1, xsq), bv[2 * jp + 1]);
                    *addr = f2u(lg0, lg1);
                }
            }
        }
    }
    __syncthreads();

    // ---- Softmax over k (lane = k): warp w handles px [16w, 16w+16); no max pass ----
    {
        float asum_l = 0.0f;
        #pragma unroll
        for (int q = 0; q < 4; q++) {
            int t0 = w * 16 + 4 * q;
            float v0 = sm[A_OFF + (t0 + 0) * ASTRIDE + l];
            float v1 = sm[A_OFF + (t0 + 1) * ASTRIDE + l];
            float v2 = sm[A_OFF + (t0 + 2) * ASTRIDE + l];
            float v3 = sm[A_OFF + (t0 + 3) * ASTRIDE + l];
            float e0 = __expf(v0), e1 = __expf(v1);
            float e2 = __expf(v2), e3 = __expf(v3);
            float s0 = e0, s1 = e1, s2 = e2, s3 = e3;
            #pragma unroll
            for (int o = 16; o > 0; o >>= 1) {
                s0 += __shfl_xor_sync(0xffffffffu, s0, o);
                s1 += __shfl_xor_sync(0xffffffffu, s1, o);
                s2 += __shfl_xor_sync(0xffffffffu, s2, o);
                s3 += __shfl_xor_sync(0xffffffffu, s3, o);
            }
            float a0 = e0 * __fdividef(1.0f, s0);
            float a1 = e1 * __fdividef(1.0f, s1);
            float a2 = e2 * __fdividef(1.0f, s2);
            float a3 = e3 * __fdividef(1.0f, s3);
            sm[A_OFF + (t0 + 0) * ASTRIDE + l] = a0;
            sm[A_OFF + (t0 + 1) * ASTRIDE + l] = a1;
            sm[A_OFF + (t0 + 2) * ASTRIDE + l] = a2;
            sm[A_OFF + (t0 + 3) * ASTRIDE + l] = a3;
            asum_l += a0 + a1 + a2 + a3;
        }
        sm[WAS_OFF + w * 32 + l] = asum_l;
    }
    __syncthreads();
    if (tid < 32) {
        float a = 0.0f;
        #pragma unroll
        for (int ww = 0; ww < 8; ww++) a += sm[WAS_OFF + ww * 32 + tid];
        sm[ASUM_OFF + tid] = a;
    }
    __syncthreads();

    // ---- Stage B: E[k][d] = sum_t A[k][t]*x[t][d]; 8k x 4d tile, k-pair acc, 2-way t split ----
    // gB = w>>2 (t-half), kbB = w&3 (k-octet, uniform per warp), db = l; d = db + 32*j.
    {
        const int gB  = w >> 2;
        const int kbB = w & 3;
        const int db  = l;

        ull acc2[4][4];
        #pragma unroll
        for (int jj = 0; jj < 4; jj++)
            #pragma unroll
            for (int j = 0; j < 4; j++) acc2[jj][j] = 0ULL;

        const int t0 = 64 * gB;
        #pragma unroll 2
        for (int tt = 0; tt < 64; tt++) {
            int t = t0 + tt;
            const float* xrow = sm + X_OFF + t * XSTRIDE + db;
            ull xx[4];
            #pragma unroll
            for (int j = 0; j < 4; j++) {
                float xv = xrow[32 * j];
                xx[j] = f2u(xv, xv);
            }
            const float* Ar = sm + A_OFF + t * ASTRIDE + 8 * kbB;
            ull av0 = *(const ull*)(Ar + 0);
            ull av1 = *(const ull*)(Ar + 2);
            ull av2 = *(const ull*)(Ar + 4);
            ull av3 = *(const ull*)(Ar + 6);
            #pragma unroll
            for (int j = 0; j < 4; j++) {
                ffma2(acc2[0][j], av0, xx[j]);
                ffma2(acc2[1][j], av1, xx[j]);
                ffma2(acc2[2][j], av2, xx[j]);
                ffma2(acc2[3][j], av3, xx[j]);
            }
        }
        __syncthreads();           // all A reads done; A region becomes Ered[d][k]

        if (gB == 0) {             // write partials: Ered row d, float offset = k
            #pragma unroll
            for (int jj = 0; jj < 4; jj++)
                #pragma unroll
                for (int j = 0; j < 4; j++) {
                    int d = db + 32 * j;
                    *(ull*)(sm + A_OFF + d * ASTRIDE + 8 * kbB + 2 * jj) = acc2[jj][j];
                }
        }
        __syncthreads();
        if (gB == 1) {             // add own partial, fold -asum*c, atomic merge
            float* Eb = out + (size_t)b * K_DIM * D_DIM;
            #pragma unroll
            for (int jj = 0; jj < 4; jj++) {
                int k0 = 8 * kbB + 2 * jj;
                float as0 = sm[ASUM_OFF + k0];
                float as1 = sm[ASUM_OFF + k0 + 1];
                #pragma unroll
                for (int j = 0; j < 4; j++) {
                    int d = db + 32 * j;
                    float2 mine = u2f(acc2[jj][j]);
                    float2 oth  = u2f(*(const ull*)(sm + A_OFF + d * ASTRIDE + k0));
                    float v0 = fmaf(-as0, sm[C_OFF + k0 * CSTRIDE + d],       mine.x + oth.x);
                    float v1 = fmaf(-as1, sm[C_OFF + (k0 + 1) * CSTRIDE + d], mine.y + oth.y);
                    atomicAdd(Eb + k0 * D_DIM + d,           v0);
                    atomicAdd(Eb + (k0 + 1) * D_DIM + d,     v1);
                }
            }
        }
    }
}

extern "C" void kernel_launch(void* const* d_in, const int* in_sizes, int n_in,
                              void* d_out, int out_size)
{
    const float* X  = (const float*)d_in[0];
    const float* CW = (const float*)d_in[1];
    const float* SC = (const float*)d_in[2];
    float* out = (float*)d_out;

    cudaFuncSetAttribute(enc_kernel, cudaFuncAttributeMaxDynamicSharedMemorySize, SMEM_BYTES);

    // zero E via async memset (graph-capturable, replaces the zero_kernel launch)
    cudaMemsetAsync(out, 0, (size_t)B_SZ * K_DIM * D_DIM * sizeof(float));
    enc_kernel<<<B_SZ * (N_PIX / TILE_T), 256, SMEM_BYTES>>>(X, CW, SC, out);
}

// round 12
// speedup vs baseline: 1.2184x; 1.0217x over previous
#include <cuda_runtime.h>
#include <cstdint>

typedef unsigned long long ull;

#define D_DIM   128
#define K_DIM   32
#define N_PIX   4096
#define B_SZ    8
#define TILE_T  128
#define XSTRIDE 130   // x row stride: conflict-free LDS.64 rows (stage A) + LDS.32 columns (stage B)
#define CSTRIDE 132   // codeword row stride (16B aligned rows)
#define ASTRIDE 34    // A / Ered row stride in floats (17 ulls)

// shared-memory layout (float offsets)
#define X_OFF    0
#define C_OFF    (TILE_T * XSTRIDE)                  // 16640
#define A_OFF    (C_OFF + K_DIM * CSTRIDE)           // 20864 (ull aligned)
#define XSQ_OFF  (A_OFF + TILE_T * ASTRIDE)          // 25216
#define XSP_OFF  (XSQ_OFF + TILE_T)                  // 25344 (2 x 128 partials)
#define S_OFF    (XSP_OFF + 2 * TILE_T)              // 25600
#define BK_OFF   (S_OFF + K_DIM)                     // 25632
#define WAS_OFF  (BK_OFF + K_DIM)                    // 25664
#define ASUM_OFF (WAS_OFF + 8 * K_DIM)               // 25920
#define SMEM_FLOATS (ASUM_OFF + K_DIM)               // 25952
#define SMEM_BYTES  (SMEM_FLOATS * 4)                // 103808 B -> 2 blocks/SM, single wave @ grid 256

// packed fp32x2 FMA (Blackwell): acc.lo += a.lo*b.lo ; acc.hi += a.hi*b.hi
__device__ __forceinline__ void ffma2(ull &acc, ull a, ull b) {
    asm("fma.rn.f32x2 %0, %1, %2, %0;" : "+l"(acc) : "l"(a), "l"(b));
}
__device__ __forceinline__ float2 u2f(ull v) {
    float2 r;
    asm("mov.b64 {%0, %1}, %2;" : "=f"(r.x), "=f"(r.y) : "l"(v));
    return r;
}
__device__ __forceinline__ ull f2u(float x, float y) {
    ull v;
    asm("mov.b64 %0, {%1, %2};" : "=l"(v) : "f"(x), "f"(y));
    return v;
}

__global__ void zero_kernel(float4* p, int n4) {
    int i = blockIdx.x * blockDim.x + threadIdx.x;
    if (i < n4) p[i] = make_float4(0.f, 0.f, 0.f, 0.f);
}

__global__ void __launch_bounds__(256, 2)
enc_kernel(const float* __restrict__ X,
           const float* __restrict__ CW,
           const float* __restrict__ SC,
           float* __restrict__ out)
{
    extern __shared__ float sm[];

    const int tid  = threadIdx.x;
    const int w    = tid >> 5;
    const int l    = tid & 31;
    const int b    = blockIdx.x >> 5;      // batch (32 tiles per batch)
    const int tile = blockIdx.x & 31;
    const int n0   = tile * TILE_T;

    // ---- load X tile [128 d][128 t] -> x_sh[t][130], folding per-pixel x^2 partials ----
    // thread: t = tid&127 (fixed), d = (tid>>7) + 2*s  -> each thread owns 64 d's of one pixel.
    {
        const float* Xb = X + (size_t)b * D_DIM * N_PIX + n0;
        const int tl = tid & 127;
        const int dh = tid >> 7;
        float ssq = 0.0f;
        #pragma unroll 8
        for (int s = 0; s < 64; s++) {
            int d = dh + 2 * s;
            float v = Xb[(size_t)d * N_PIX + tl];
            sm[X_OFF + tl * XSTRIDE + d] = v;
            ssq = fmaf(v, v, ssq);
        }
        sm[XSP_OFF + dh * TILE_T + tl] = ssq;

        // codewords: float4 path (4 LDG.128 + 4 STS.128 per thread, coalesced, conflict-free)
        #pragma unroll
        for (int s = 0; s < 4; s++) {
            int c = tid + 256 * s;             // 0..1023 quads
            int k = c >> 5;
            int dc = (c & 31) * 4;
            float4 v = *(const float4*)(CW + 4 * c);
            *(float4*)(sm + C_OFF + k * CSTRIDE + dc) = v;
        }
    }
    __syncthreads();

    // ---- finalize xsq; csq*scale per codeword ----
    if (tid < TILE_T)
        sm[XSQ_OFF + tid] = sm[XSP_OFF + tid] + sm[XSP_OFF + TILE_T + tid];
    #pragma unroll
    for (int jj = 0; jj < 4; jj++) {
        int k = 4 * w + jj;
        const float* row = sm + C_OFF + k * CSTRIDE;
        float2 v0 = *(const float2*)(row + 2 * l);
        float2 v1 = *(const float2*)(row + 64 + 2 * l);
        float ss = v0.x * v0.x + v0.y * v0.y + v1.x * v1.x + v1.y * v1.y;
        #pragma unroll
        for (int o = 16; o > 0; o >>= 1) ss += __shfl_xor_sync(0xffffffffu, ss, o);
        if (l == 0) {
            float sc = SC[k];
            sm[S_OFF + k]  = sc;
            sm[BK_OFF + k] = ss * sc;
        }
    }
    __syncthreads();

    // ---- Stage A: cross[t][k] = sum_d x[t][d]*c[k][d]; 8t x 4k tile, d-pair acc, 2-way d split ----
    // g = w>>2 (d-half 64), lanes: tb = l&15, lh = l>>4; kb = 2*(w&3)+lh in [0,8); k = 4kb+jj.
    const int g  = w >> 2;
    const int tb = l & 15;
    const int lh = l >> 4;
    {
        const int kb = 2 * (w & 3) + lh;

        ull acc[8][4];
        #pragma unroll
        for (int i = 0; i < 8; i++)
            #pragma unroll
            for (int jj = 0; jj < 4; jj++) acc[i][jj] = 0ULL;

        const float* xr = sm + X_OFF + tb * XSTRIDE + 64 * g;
        const float* cr = sm + C_OFF + (4 * kb) * CSTRIDE + 64 * g;

        #pragma unroll 4
        for (int dp = 0; dp < 32; dp++) {
            ull cv[4];
            #pragma unroll
            for (int jj = 0; jj < 4; jj++)
                cv[jj] = *(const ull*)(cr + jj * CSTRIDE + 2 * dp);
            #pragma unroll
            for (int i = 0; i < 8; i++) {
                ull xv = *(const ull*)(xr + (16 * i) * XSTRIDE + 2 * dp);
                ffma2(acc[i][0], xv, cv[0]);
                ffma2(acc[i][1], xv, cv[1]);
                ffma2(acc[i][2], xv, cv[2]);
                ffma2(acc[i][3], xv, cv[3]);
            }
        }

        // g==1 writes partial cross pairs (k,k+1) into A[t][k] (float offset = k)
        if (g == 1) {
            #pragma unroll
            for (int i = 0; i < 8; i++) {
                int t = tb + 16 * i;
                #pragma unroll
                for (int jp = 0; jp < 2; jp++) {
                    float2 p0 = u2f(acc[i][2 * jp]);
                    float2 p1 = u2f(acc[i][2 * jp + 1]);
                    *(ull*)(sm + A_OFF + t * ASTRIDE + 4 * kb + 2 * jp) =
                        f2u(p0.x + p0.y, p1.x + p1.y);
                }
            }
        }
        __syncthreads();
        // g==0 adds its partial, computes logits, writes back in place
        if (g == 0) {
            float sv[4], bv[4];
            #pragma unroll
            for (int jj = 0; jj < 4; jj++) {
                sv[jj] = sm[S_OFF + 4 * kb + jj];
                bv[jj] = sm[BK_OFF + 4 * kb + jj];
            }
            #pragma unroll
            for (int i = 0; i < 8; i++) {
                int t = tb + 16 * i;
                float xsq = sm[XSQ_OFF + t];
                #pragma unroll
                for (int jp = 0; jp < 2; jp++) {
                    ull* addr = (ull*)(sm + A_OFF + t * ASTRIDE + 4 * kb + 2 * jp);
                    float2 oth = u2f(*addr);
                    float2 p0 = u2f(acc[i][2 * jp]);
                    float2 p1 = u2f(acc[i][2 * jp + 1]);
                    float cr0 = oth.x + p0.x + p0.y;
                    float cr1 = oth.y + p1.x + p1.y;
                    float lg0 = fmaf(sv[2 * jp],     fmaf(-2.0f, cr0, xsq), bv[2 * jp]);
                    float lg1 = fmaf(sv[2 * jp + 1], fmaf(-2.0f, cr1, xsq), bv[2 * jp + 1]);
                    *addr = f2u(lg0, lg1);
                }
            }
        }
    }
    __syncthreads();

    // ---- Softmax over k (lane = k): warp w handles px [16w, 16w+16); no max pass ----
    {
        float asum_l = 0.0f;
        #pragma unroll
        for (int q = 0; q < 4; q++) {
            int t0 = w * 16 + 4 * q;
            float v0 = sm[A_OFF + (t0 + 0) * ASTRIDE + l];
            float v1 = sm[A_OFF + (t0 + 1) * ASTRIDE + l];
            float v2 = sm[A_OFF + (t0 + 2) * ASTRIDE + l];
            float v3 = sm[A_OFF + (t0 + 3) * ASTRIDE + l];
            float e0 = __expf(v0), e1 = __expf(v1);
            float e2 = __expf(v2), e3 = __expf(v3);
            float s0 = e0, s1 = e1, s2 = e2, s3 = e3;
            #pragma unroll
            for (int o = 16; o > 0; o >>= 1) {
                s0 += __shfl_xor_sync(0xffffffffu, s0, o);
                s1 += __shfl_xor_sync(0xffffffffu, s1, o);
                s2 += __shfl_xor_sync(0xffffffffu, s2, o);
                s3 += __shfl_xor_sync(0xffffffffu, s3, o);
            }
            float a0 = e0 * __fdividef(1.0f, s0);
            float a1 = e1 * __fdividef(1.0f, s1);
            float a2 = e2 * __fdividef(1.0f, s2);
            float a3 = e3 * __fdividef(1.0f, s3);
            sm[A_OFF + (t0 + 0) * ASTRIDE + l] = a0;
            sm[A_OFF + (t0 + 1) * ASTRIDE + l] = a1;
            sm[A_OFF + (t0 + 2) * ASTRIDE + l] = a2;
            sm[A_OFF + (t0 + 3) * ASTRIDE + l] = a3;
            asum_l += a0 + a1 + a2 + a3;
        }
        sm[WAS_OFF + w * 32 + l] = asum_l;
    }
    __syncthreads();
    if (tid < 32) {
        float a = 0.0f;
        #pragma unroll
        for (int ww = 0; ww < 8; ww++) a += sm[WAS_OFF + ww * 32 + tid];
        sm[ASUM_OFF + tid] = a;
    }
    __syncthreads();

    // ---- Stage B: E[k][d] = sum_t A[k][t]*x[t][d]; 8k x 4d tile, k-pair acc, 2-way t split ----
    // gB = w>>2 (t-half), kbB = w&3 (k-octet, uniform per warp), db = l; d = db + 32*j.
    {
        const int gB  = w >> 2;
        const int kbB = w & 3;
        const int db  = l;

        ull acc2[4][4];
        #pragma unroll
        for (int jj = 0; jj < 4; jj++)
            #pragma unroll
            for (int j = 0; j < 4; j++) acc2[jj][j] = 0ULL;

        const int t0 = 64 * gB;
        #pragma unroll 2
        for (int tt = 0; tt < 64; tt++) {
            int t = t0 + tt;
            const float* xrow = sm + X_OFF + t * XSTRIDE + db;
            ull xx[4];
            #pragma unroll
            for (int j = 0; j < 4; j++) {
                float xv = xrow[32 * j];
                xx[j] = f2u(xv, xv);
            }
            const float* Ar = sm + A_OFF + t * ASTRIDE + 8 * kbB;
            ull av0 = *(const ull*)(Ar + 0);
            ull av1 = *(const ull*)(Ar + 2);
            ull av2 = *(const ull*)(Ar + 4);
            ull av3 = *(const ull*)(Ar + 6);
            #pragma unroll
            for (int j = 0; j < 4; j++) {
                ffma2(acc2[0][j], av0, xx[j]);
                ffma2(acc2[1][j], av1, xx[j]);
                ffma2(acc2[2][j], av2, xx[j]);
                ffma2(acc2[3][j], av3, xx[j]);
            }
        }
        __syncthreads();           // all A reads done; A region becomes Ered[d][k]

        if (gB == 0) {             // write partials: Ered row d, float offset = k
            #pragma unroll
            for (int jj = 0; jj < 4; jj++)
                #pragma unroll
                for (int j = 0; j < 4; j++) {
                    int d = db + 32 * j;
                    *(ull*)(sm + A_OFF + d * ASTRIDE + 8 * kbB + 2 * jj) = acc2[jj][j];
                }
        }
        __syncthreads();
        if (gB == 1) {             // add own partial, fold -asum*c, atomic merge
            float* Eb = out + (size_t)b * K_DIM * D_DIM;
            #pragma unroll
            for (int jj = 0; jj < 4; jj++) {
                int k0 = 8 * kbB + 2 * jj;
                float as0 = sm[ASUM_OFF + k0];
                float as1 = sm[ASUM_OFF + k0 + 1];
                #pragma unroll
                for (int j = 0; j < 4; j++) {
                    int d = db + 32 * j;
                    float2 mine = u2f(acc2[jj][j]);
                    float2 oth  = u2f(*(const ull*)(sm + A_OFF + d * ASTRIDE + k0));
                    float v0 = fmaf(-as0, sm[C_OFF + k0 * CSTRIDE + d],       mine.x + oth.x);
                    float v1 = fmaf(-as1, sm[C_OFF + (k0 + 1) * CSTRIDE + d], mine.y + oth.y);
                    atomicAdd(Eb + k0 * D_DIM + d,           v0);
                    atomicAdd(Eb + (k0 + 1) * D_DIM + d,     v1);
                }
            }
        }
    }
}

extern "C" void kernel_launch(void* const* d_in, const int* in_sizes, int n_in,
                              void* d_out, int out_size)
{
    const float* X  = (const float*)d_in[0];
    const float* CW = (const float*)d_in[1];
    const float* SC = (const float*)d_in[2];
    float* out = (float*)d_out;

    cudaFuncSetAttribute(enc_kernel, cudaFuncAttributeMaxDynamicSharedMemorySize, SMEM_BYTES);

    const int OUT_N4 = (B_SZ * K_DIM * D_DIM) / 4;      // 8192 float4
    zero_kernel<<<OUT_N4 / 256, 256>>>((float4*)out, OUT_N4);
    enc_kernel<<<B_SZ * (N_PIX / TILE_T), 256, SMEM_BYTES>>>(X, CW, SC, out);
}

// round 13
// speedup vs baseline: 1.3250x; 1.0875x over previous
#include <cuda_runtime.h>
#include <cstdint>

typedef unsigned long long ull;

#define D_DIM   128
#define K_DIM   32
#define N_PIX   4096
#define B_SZ    8
#define TILE_T  128
#define XSTRIDE 130   // x row stride: conflict-free LDS.64 rows (stage A) + LDS.32 columns (stage B)
#define CSTRIDE 132   // codeword row stride (16B aligned rows)
#define ASTRIDE 34    // A / Ered row stride in floats (17 ulls)

// shared-memory layout (float offsets)
#define X_OFF    0
#define C_OFF    (TILE_T * XSTRIDE)                  // 16640
#define A_OFF    (C_OFF + K_DIM * CSTRIDE)           // 20864 (ull aligned)
#define XSQ_OFF  (A_OFF + TILE_T * ASTRIDE)          // 25216
#define XSP_OFF  (XSQ_OFF + TILE_T)                  // 25344 (2 x 128 partials)
#define S_OFF    (XSP_OFF + 2 * TILE_T)              // 25600
#define BK_OFF   (S_OFF + K_DIM)                     // 25632
#define ASUM_OFF (BK_OFF + K_DIM)                    // 25664
#define SMEM_FLOATS (ASUM_OFF + K_DIM)               // 25696
#define SMEM_BYTES  (SMEM_FLOATS * 4)                // 102784 B -> 2 blocks/SM, single wave @ grid 256

// packed fp32x2 FMA (Blackwell): acc.lo += a.lo*b.lo ; acc.hi += a.hi*b.hi
__device__ __forceinline__ void ffma2(ull &acc, ull a, ull b) {
    asm("fma.rn.f32x2 %0, %1, %2, %0;" : "+l"(acc) : "l"(a), "l"(b));
}
__device__ __forceinline__ float2 u2f(ull v) {
    float2 r;
    asm("mov.b64 {%0, %1}, %2;" : "=f"(r.x), "=f"(r.y) : "l"(v));
    return r;
}
__device__ __forceinline__ ull f2u(float x, float y) {
    ull v;
    asm("mov.b64 %0, {%1, %2};" : "=l"(v) : "f"(x), "f"(y));
    return v;
}

__global__ void zero_kernel(float4* p, int n4) {
    int i = blockIdx.x * blockDim.x + threadIdx.x;
    if (i < n4) p[i] = make_float4(0.f, 0.f, 0.f, 0.f);
}

__global__ void __launch_bounds__(256, 2)
enc_kernel(const float* __restrict__ X,
           const float* __restrict__ CW,
           const float* __restrict__ SC,
           float* __restrict__ out)
{
    extern __shared__ float sm[];

    const int tid  = threadIdx.x;
    const int w    = tid >> 5;
    const int l    = tid & 31;
    const int b    = blockIdx.x >> 5;      // batch (32 tiles per batch)
    const int tile = blockIdx.x & 31;
    const int n0   = tile * TILE_T;

    // ---- load C (with fused csq warp-reduce), then X (with fused x^2 partials) ----
    {
        // zero asum accumulators (used by softmax smem atomics later)
        if (tid < K_DIM) sm[ASUM_OFF + tid] = 0.0f;

        // codewords: quad c = tid + 256*s belongs to row k = w + 8*s, quad index l.
        // So per s, a warp-reduce of the lane quad-sums gives csq[w + 8*s] directly.
        float qss[4];
        #pragma unroll
        for (int s = 0; s < 4; s++) {
            int c = tid + 256 * s;             // 0..1023 quads
            int k = c >> 5;                    // = w + 8*s (uniform per warp)
            int dc = (c & 31) * 4;             // = 4*l
            float4 v = *(const float4*)(CW + 4 * c);
            *(float4*)(sm + C_OFF + k * CSTRIDE + dc) = v;
            qss[s] = v.x * v.x + v.y * v.y + v.z * v.z + v.w * v.w;
        }
        float sc_l = (l < 4) ? SC[w + 8 * l] : 0.0f;   // lane j holds SC[w+8j]
        #pragma unroll
        for (int o = 16; o > 0; o >>= 1) {
            qss[0] += __shfl_xor_sync(0xffffffffu, qss[0], o);
            qss[1] += __shfl_xor_sync(0xffffffffu, qss[1], o);
            qss[2] += __shfl_xor_sync(0xffffffffu, qss[2], o);
            qss[3] += __shfl_xor_sync(0xffffffffu, qss[3], o);
        }
        if (l < 4) {
            int k = w + 8 * l;
            float ss = (l == 0) ? qss[0] : (l == 1) ? qss[1] : (l == 2) ? qss[2] : qss[3];
            sm[S_OFF + k]  = sc_l;
            sm[BK_OFF + k] = ss * sc_l;
        }

        // X tile [128 d][128 t] -> x_sh[t][130], folding per-pixel x^2 partials.
        // thread: t = tid&127 (fixed), d = (tid>>7) + 2*s.
        const float* Xb = X + (size_t)b * D_DIM * N_PIX + n0;
        const int tl = tid & 127;
        const int dh = tid >> 7;
        float ssq = 0.0f;
        #pragma unroll 8
        for (int s = 0; s < 64; s++) {
            int d = dh + 2 * s;
            float v = Xb[(size_t)d * N_PIX + tl];
            sm[X_OFF + tl * XSTRIDE + d] = v;
            ssq = fmaf(v, v, ssq);
        }
        sm[XSP_OFF + dh * TILE_T + tl] = ssq;
    }
    __syncthreads();

    // ---- finalize xsq ----
    if (tid < TILE_T)
        sm[XSQ_OFF + tid] = sm[XSP_OFF + tid] + sm[XSP_OFF + TILE_T + tid];
    __syncthreads();

    // ---- Stage A: cross[t][k] = sum_d x[t][d]*c[k][d]; 8t x 4k tile, d-pair acc, 2-way d split ----
    // g = w>>2 (d-half 64), lanes: tb = l&15, lh = l>>4; kb = 2*(w&3)+lh in [0,8); k = 4kb+jj.
    const int g  = w >> 2;
    const int tb = l & 15;
    const int lh = l >> 4;
    {
        const int kb = 2 * (w & 3) + lh;

        ull acc[8][4];
        #pragma unroll
        for (int i = 0; i < 8; i++)
            #pragma unroll
            for (int jj = 0; jj < 4; jj++) acc[i][jj] = 0ULL;

        const float* xr = sm + X_OFF + tb * XSTRIDE + 64 * g;
        const float* cr = sm + C_OFF + (4 * kb) * CSTRIDE + 64 * g;

        #pragma unroll 2
        for (int dp = 0; dp < 32; dp++) {
            ull cv[4];
            #pragma unroll
            for (int jj = 0; jj < 4; jj++)
                cv[jj] = *(const ull*)(cr + jj * CSTRIDE + 2 * dp);
            #pragma unroll
            for (int i = 0; i < 8; i++) {
                ull xv = *(const ull*)(xr + (16 * i) * XSTRIDE + 2 * dp);
                ffma2(acc[i][0], xv, cv[0]);
                ffma2(acc[i][1], xv, cv[1]);
                ffma2(acc[i][2], xv, cv[2]);
                ffma2(acc[i][3], xv, cv[3]);
            }
        }

        // g==1 writes partial cross pairs (k,k+1) into A[t][k] (float offset = k)
        if (g == 1) {
            #pragma unroll
            for (int i = 0; i < 8; i++) {
                int t = tb + 16 * i;
                #pragma unroll
                for (int jp = 0; jp < 2; jp++) {
                    float2 p0 = u2f(acc[i][2 * jp]);
                    float2 p1 = u2f(acc[i][2 * jp + 1]);
                    *(ull*)(sm + A_OFF + t * ASTRIDE + 4 * kb + 2 * jp) =
                        f2u(p0.x + p0.y, p1.x + p1.y);
                }
            }
        }
        __syncthreads();
        // g==0 adds its partial, computes logits, writes back in place
        if (g == 0) {
            float sv[4], bv[4];
            #pragma unroll
            for (int jj = 0; jj < 4; jj++) {
                sv[jj] = sm[S_OFF + 4 * kb + jj];
                bv[jj] = sm[BK_OFF + 4 * kb + jj];
            }
            #pragma unroll
            for (int i = 0; i < 8; i++) {
                int t = tb + 16 * i;
                float xsq = sm[XSQ_OFF + t];
                #pragma unroll
                for (int jp = 0; jp < 2; jp++) {
                    ull* addr = (ull*)(sm + A_OFF + t * ASTRIDE + 4 * kb + 2 * jp);
                    float2 oth = u2f(*addr);
                    float2 p0 = u2f(acc[i][2 * jp]);
                    float2 p1 = u2f(acc[i][2 * jp + 1]);
                    float cr0 = oth.x + p0.x + p0.y;
                    float cr1 = oth.y + p1.x + p1.y;
                    float lg0 = fmaf(sv[2 * jp],     fmaf(-2.0f, cr0, xsq), bv[2 * jp]);
                    float lg1 = fmaf(sv[2 * jp + 1], fmaf(-2.0f, cr1, xsq), bv[2 * jp + 1]);
                    *addr = f2u(lg0, lg1);
                }
            }
        }
    }
    __syncthreads();

    // ---- Softmax over k (lane = k): warp w handles px [16w, 16w+16); no max pass ----
    // per-warp asum partial merged via smem float atomics (spread addresses, 1 per lane).
    {
        float asum_l = 0.0f;
        #pragma unroll
        for (int q = 0; q < 4; q++) {
            int t0 = w * 16 + 4 * q;
            float v0 = sm[A_OFF + (t0 + 0) * ASTRIDE + l];
            float v1 = sm[A_OFF + (t0 + 1) * ASTRIDE + l];
            float v2 = sm[A_OFF + (t0 + 2) * ASTRIDE + l];
            float v3 = sm[A_OFF + (t0 + 3) * ASTRIDE + l];
            float e0 = __expf(v0), e1 = __expf(v1);
            float e2 = __expf(v2), e3 = __expf(v3);
            float s0 = e0, s1 = e1, s2 = e2, s3 = e3;
            #pragma unroll
            for (int o = 16; o > 0; o >>= 1) {
                s0 += __shfl_xor_sync(0xffffffffu, s0, o);
                s1 += __shfl_xor_sync(0xffffffffu, s1, o);
                s2 += __shfl_xor_sync(0xffffffffu, s2, o);
                s3 += __shfl_xor_sync(0xffffffffu, s3, o);
            }
            float a0 = e0 * __fdividef(1.0f, s0);
            float a1 = e1 * __fdividef(1.0f, s1);
            float a2 = e2 * __fdividef(1.0f, s2);
            float a3 = e3 * __fdividef(1.0f, s3);
            sm[A_OFF + (t0 + 0) * ASTRIDE + l] = a0;
            sm[A_OFF + (t0 + 1) * ASTRIDE + l] = a1;
            sm[A_OFF + (t0 + 2) * ASTRIDE + l] = a2;
            sm[A_OFF + (t0 + 3) * ASTRIDE + l] = a3;
            asum_l += a0 + a1 + a2 + a3;
        }
        atomicAdd(sm + ASUM_OFF + l, asum_l);      // lane l = codeword l
    }
    __syncthreads();

    // ---- Stage B: E[k][d] = sum_t A[k][t]*x[t][d]; 8k x 4d tile, k-pair acc, 2-way t split ----
    // gB = w>>2 (t-half), kbB = w&3 (k-octet, uniform per warp), db = l; d = db + 32*j.
    {
        const int gB  = w >> 2;
        const int kbB = w & 3;
        const int db  = l;

        ull acc2[4][4];
        #pragma unroll
        for (int jj = 0; jj < 4; jj++)
            #pragma unroll
            for (int j = 0; j < 4; j++) acc2[jj][j] = 0ULL;

        const int t0 = 64 * gB;
        #pragma unroll 2
        for (int tt = 0; tt < 64; tt++) {
            int t = t0 + tt;
            const float* xrow = sm + X_OFF + t * XSTRIDE + db;
            ull xx[4];
            #pragma unroll
            for (int j = 0; j < 4; j++) {
                float xv = xrow[32 * j];
                xx[j] = f2u(xv, xv);
            }
            const float* Ar = sm + A_OFF + t * ASTRIDE + 8 * kbB;
            ull av0 = *(const ull*)(Ar + 0);
            ull av1 = *(const ull*)(Ar + 2);
            ull av2 = *(const ull*)(Ar + 4);
            ull av3 = *(const ull*)(Ar + 6);
            #pragma unroll
            for (int j = 0; j < 4; j++) {
                ffma2(acc2[0][j], av0, xx[j]);
                ffma2(acc2[1][j], av1, xx[j]);
                ffma2(acc2[2][j], av2, xx[j]);
                ffma2(acc2[3][j], av3, xx[j]);
            }
        }
        __syncthreads();           // all A reads done; A region becomes Ered[d][k]

        if (gB == 0) {             // write partials: Ered row d, float offset = k
            #pragma unroll
            for (int jj = 0; jj < 4; jj++)
                #pragma unroll
                for (int j = 0; j < 4; j++) {
                    int d = db + 32 * j;
                    *(ull*)(sm + A_OFF + d * ASTRIDE + 8 * kbB + 2 * jj) = acc2[jj][j];
                }
        }
        __syncthreads();
        if (gB == 1) {             // add own partial, fold -asum*c, atomic merge
            float* Eb = out + (size_t)b * K_DIM * D_DIM;
            #pragma unroll
            for (int jj = 0; jj < 4; jj++) {
                int k0 = 8 * kbB + 2 * jj;
                float as0 = sm[ASUM_OFF + k0];
                float as1 = sm[ASUM_OFF + k0 + 1];
                #pragma unroll
                for (int j = 0; j < 4; j++) {
                    int d = db + 32 * j;
                    float2 mine = u2f(acc2[jj][j]);
                    float2 oth  = u2f(*(const ull*)(sm + A_OFF + d * ASTRIDE + k0));
                    float v0 = fmaf(-as0, sm[C_OFF + k0 * CSTRIDE + d],       mine.x + oth.x);
                    float v1 = fmaf(-as1, sm[C_OFF + (k0 + 1) * CSTRIDE + d], mine.y + oth.y);
                    atomicAdd(Eb + k0 * D_DIM + d,           v0);
                    atomicAdd(Eb + (k0 + 1) * D_DIM + d,     v1);
                }
            }
        }
    }
}

extern "C" void kernel_launch(void* const* d_in, const int* in_sizes, int n_in,
                              void* d_out, int out_size)
{
    const float* X  = (const float*)d_in[0];
    const float* CW = (const float*)d_in[1];
    const float* SC = (const float*)d_in[2];
    float* out = (float*)d_out;

    cudaFuncSetAttribute(enc_kernel, cudaFuncAttributeMaxDynamicSharedMemorySize, SMEM_BYTES);

    const int OUT_N4 = (B_SZ * K_DIM * D_DIM) / 4;      // 8192 float4
    zero_kernel<<<OUT_N4 / 256, 256>>>((float4*)out, OUT_N4);
    enc_kernel<<<B_SZ * (N_PIX / TILE_T), 256, SMEM_BYTES>>>(X, CW, SC, out);
}